// round 10
// baseline (speedup 1.0000x reference)
#include <cuda_runtime.h>
#include <math.h>

// Problem constants
#define Bn   8
#define Cin  128
#define Cout 128
#define Hn   112
#define Wn   112
#define Kk   9
#define HW   (Hn*Wn)            // 12544
#define NPIX (Bn*HW)            // 100352
#define KDIM (Cin*Kk)           // 1152

#define CH   4                  // main: channels per chunk
#define NCH  (Cin/CH)           // 32 chunks
#define KCH  (CH*Kk)            // 36 logical k per chunk
#define KP   40                 // main: padded k per chunk
#define KST  40                 // main: smem row stride (words)

#define OCH   8                 // offmask: channels per chunk
#define ONCH  (Cin/OCH)         // 16 chunks
#define OKP   72                // offmask: k per chunk (8*9 = 9 k-steps exactly)

// ---------------- device scratch ----------------
__device__ float4 g_wP4[NCH*Cout*(KP/4)];      // main weights, permuted tf32
__device__ float4 g_owP4[ONCH*32*(OKP/4)];     // offmask weights [chunk][n=32][72], permuted tf32
__device__ float4 g_meta_w[NPIX*Kk];           // bilinear tap weights (mask folded)
__device__ int4   g_meta_off[NPIX*Kk];         // clamped plane offsets y*W+x

static __device__ __forceinline__ float to_tf32(float x) {
    float r;
    asm("cvt.rna.tf32.f32 %0, %1;" : "=f"(r) : "f"(x));
    return r;
}
// storage position of logical k within an 8-wide k-step (frag-pair interleave)
static __device__ __forceinline__ int kpos(int kkl) {
    int j = kkl & 7;
    return (kkl >> 3) * 8 + 2 * (j & 3) + (j >> 2);
}
// per-row circular rotation (bank de-conflict), stride 40
static __device__ __forceinline__ int srow40(int p, int pos) {
    int pp = pos + 2 * ((p >> 2) & 3);
    if (pp >= 40) pp -= 40;
    return p * 40 + pp;
}
// same, stride 72
static __device__ __forceinline__ int srow72(int p, int pos) {
    int pp = pos + 2 * ((p >> 2) & 3);
    if (pp >= 72) pp -= 72;
    return p * 72 + pp;
}

// ---------------- kernel 0: weight prep (permute + tf32 round) ----------------
__global__ void prep_weights_kernel(const float* __restrict__ w,
                                    const float* __restrict__ ow,
                                    const float* __restrict__ mw) {
    int idx = blockIdx.x * 256 + threadIdx.x;
    if (idx < NCH * Cout * KP) {
        int ch = idx / (Cout * KP);
        int r  = idx - ch * (Cout * KP);
        int o  = r / KP;
        int p  = r - o * KP;
        int ks = p >> 3, q = p & 7;
        int j  = (q & 1) * 4 + (q >> 1);      // inverse of kpos
        int kkl = ks * 8 + j;
        float v = 0.f;
        if (kkl < KCH) {
            int c  = ch * CH + kkl / 9;
            int kk = kkl - (kkl / 9) * 9;
            v = to_tf32(w[(size_t)o * KDIM + c * 9 + kk]);
        }
        ((float*)g_wP4)[idx] = v;
    }
    if (idx < ONCH * 32 * OKP) {              // 36864
        int ch = idx / (32 * OKP);
        int r  = idx - ch * (32 * OKP);
        int n  = r / OKP;
        int p  = r - n * OKP;
        int ks = p >> 3, q = p & 7;
        int j  = (q & 1) * 4 + (q >> 1);
        int kkl = ks * 8 + j;                 // 0..71
        int c   = ch * OCH + kkl / 9;
        int kk  = kkl - (kkl / 9) * 9;
        int gk  = c * 9 + kk;
        float v = 0.f;
        if (n < 18)      v = to_tf32(ow[(size_t)n * KDIM + gk]);
        else if (n < 27) v = to_tf32(mw[(size_t)(n - 18) * KDIM + gk]);
        ((float*)g_owP4)[idx] = v;
    }
}

// ---------------- kernel 1: offmask conv via TF32 MMA -> sampling metadata ----------------
// Block: 256 threads = 8 warps; tile 64 px (M) x 32 out (N, 28 used), K=1152 in 16 chunks of 72.
__global__ void __launch_bounds__(256)
offmask_kernel(const float* __restrict__ x,
               const float* __restrict__ ob,
               const float* __restrict__ mb) {
    __shared__ __align__(16) float s_x[64 * OKP];    // 18432 B
    __shared__ __align__(16) float s_ww[32 * OKP];   //  9216 B
    __shared__ float s_r[64 * 32];                   //  8192 B

    const int tid  = threadIdx.x;
    const int pix0 = blockIdx.x * 64;
    const int b    = pix0 / HW;
    const float* xb = x + (size_t)b * Cin * HW;

    const int lane = tid & 31;
    const int wid  = tid >> 5;
    const int m0   = (wid & 3) * 16;
    const int n0   = (wid >> 2) * 16;
    const int arow = lane >> 2;
    const int acol = lane & 3;

    // both halves' pixel coords for this lane (lane = pixel-within-half)
    const int remL = (pix0 + lane) - b * HW;
    const int h0c  = remL / Wn, w0c = remL - (remL / Wn) * Wn;
    const int remH = (pix0 + 32 + lane) - b * HW;
    const int h1c  = remH / Wn, w1c = remH - (remH / Wn) * Wn;

    float acc[2][4];
#pragma unroll
    for (int na = 0; na < 2; na++)
#pragma unroll
        for (int q = 0; q < 4; q++) acc[na][q] = 0.f;

    for (int ch = 0; ch < ONCH; ch++) {
        // ---- stage weights (576 float4) ----
        const float4* wp = g_owP4 + ch * 576;
        for (int i = tid; i < 576; i += 256)
            ((float4*)s_ww)[i] = __ldg(wp + i);

        // ---- stage taps: 18 tasks per warp; lanes = 32 consecutive pixels, one tap ----
#pragma unroll
        for (int t = 0; t < 18; t++) {
            int T = wid * 18 + t;               // 0..143
            int kkl = T >> 1, half = T & 1;
            int p = half * 32 + lane;
            int cc = kkl / 9, tk = kkl - (kkl / 9) * 9;
            int di = tk / 3, dj = tk - (tk / 3) * 3;
            int hh = half ? h1c : h0c;
            int ww = half ? w1c : w0c;
            int y = hh - 1 + di, xx = ww - 1 + dj;
            bool ok = ((unsigned)y < (unsigned)Hn) && ((unsigned)xx < (unsigned)Wn);
            float v = ok ? __ldg(xb + (size_t)(ch * OCH + cc) * HW + y * Wn + xx) : 0.f;
            s_x[srow72(p, kpos(kkl))] = to_tf32(v);
        }
        __syncthreads();

        // ---- 9 k-steps of MMA ----
#pragma unroll
        for (int ks = 0; ks < 9; ks++) {
            const int ko = ks * 8 + 2 * acol;
            uint2 lo = *(const uint2*)(s_x + srow72(m0 + arow, ko));
            uint2 hi = *(const uint2*)(s_x + srow72(m0 + arow + 8, ko));
#pragma unroll
            for (int na = 0; na < 2; na++) {
                uint2 bb = *(const uint2*)(s_ww + (n0 + na * 8 + arow) * OKP + ko);
                asm volatile(
                    "mma.sync.aligned.m16n8k8.row.col.f32.tf32.tf32.f32 "
                    "{%0,%1,%2,%3}, {%4,%5,%6,%7}, {%8,%9}, {%0,%1,%2,%3};"
                    : "+f"(acc[na][0]), "+f"(acc[na][1]),
                      "+f"(acc[na][2]), "+f"(acc[na][3])
                    : "r"(lo.x), "r"(hi.x), "r"(lo.y), "r"(hi.y),
                      "r"(bb.x), "r"(bb.y));
            }
        }
        __syncthreads();
    }

    // ---- dump accumulators to smem ----
#pragma unroll
    for (int na = 0; na < 2; na++) {
        int col = n0 + na * 8 + 2 * acol;
        int r0 = m0 + arow, r1 = r0 + 8;
        s_r[r0 * 32 + col]     = acc[na][0];
        s_r[r0 * 32 + col + 1] = acc[na][1];
        s_r[r1 * 32 + col]     = acc[na][2];
        s_r[r1 * 32 + col + 1] = acc[na][3];
    }
    __syncthreads();

    // ---- metadata epilogue (fp32): 4 threads per pixel ----
    const int px = tid >> 2;
    const int ph = tid & 3;
    const int pix = pix0 + px;
    const int rem = pix - b * HW;
    const int h  = rem / Wn;
    const int wc = rem - h * Wn;
    const float* rr = s_r + px * 32;

#pragma unroll
    for (int t = 0; t < 3; t++) {
        int k = ph + 4 * t;
        if (k >= 9) break;
        float dy = rr[2 * k]     + __ldg(ob + 2 * k);
        float dx = rr[2 * k + 1] + __ldg(ob + 2 * k + 1);
        float mraw = rr[18 + k]  + __ldg(mb + k);
        float mval = 2.f / (1.f + expf(-mraw));
        int ki = k / 3, kj = k - ki * 3;
        float ys = (float)(h - 1 + ki) + dy;
        float xs = (float)(wc - 1 + kj) + dx;
        float y0f = floorf(ys), x0f = floorf(xs);
        float ly = ys - y0f, lx = xs - x0f;
        int y0 = (int)y0f, x0 = (int)x0f;
        int y1 = y0 + 1, x1 = x0 + 1;
        float vy0 = ((unsigned)y0 < (unsigned)Hn) ? 1.f : 0.f;
        float vy1 = ((unsigned)y1 < (unsigned)Hn) ? 1.f : 0.f;
        float vx0 = ((unsigned)x0 < (unsigned)Wn) ? 1.f : 0.f;
        float vx1 = ((unsigned)x1 < (unsigned)Wn) ? 1.f : 0.f;
        float w00 = mval * (1.f - ly) * (1.f - lx) * vy0 * vx0;
        float w01 = mval * (1.f - ly) * lx          * vy0 * vx1;
        float w10 = mval * ly          * (1.f - lx) * vy1 * vx0;
        float w11 = mval * ly          * lx          * vy1 * vx1;
        int y0c = min(max(y0, 0), Hn - 1), y1c = min(max(y1, 0), Hn - 1);
        int x0c = min(max(x0, 0), Wn - 1), x1c = min(max(x1, 0), Wn - 1);
        int oy0 = y0c * Wn, oy1 = y1c * Wn;
        g_meta_w[pix * 9 + k]   = make_float4(w00, w01, w10, w11);
        g_meta_off[pix * 9 + k] = make_int4(oy0 + x0c, oy0 + x1c, oy1 + x0c, oy1 + x1c);
    }
}

// ---------------- kernel 2: pipelined fused sample + TF32 MMA ----------------
// Sampling remapped: warp task = (kkl, pixel-half); lanes = 32 consecutive pixels.
__global__ void __launch_bounds__(256, 2)
main_kernel(const float* __restrict__ x,
            const float* __restrict__ bias,
            float* __restrict__ out) {
    extern __shared__ char dyn[];
    float4* s_mw = (float4*)dyn;                         //  9216 B
    int4*   s_mo = (int4*)(dyn + 9216);                  //  9216 B
    float*  s_s  = (float*)(dyn + 18432);                // 2 x 64*40*4  = 20480 B
    float*  s_w  = (float*)(dyn + 18432 + 20480);        // 2 x 128*40*4 = 40960 B

    const int tid  = threadIdx.x;
    const int pix0 = blockIdx.x * 64;
    const int b    = pix0 / HW;
    const int hw0  = pix0 - b * HW;

    for (int i = tid; i < 576; i += 256) {
        s_mw[i] = g_meta_w[pix0 * 9 + i];
        s_mo[i] = g_meta_off[pix0 * 9 + i];
    }
    // zero pad lanes (logical kkl 36..39) in both buffers, rotation-aware
    for (int i = tid; i < 512; i += 256) {
        int bu = i >> 8, r = i & 255;
        int p = r >> 2, pj = r & 3;
        s_s[bu * 2560 + srow40(p, 33 + 2 * pj)] = 0.f;
    }
    __syncthreads();

    const int lane = tid & 31;
    const int wid  = tid >> 5;
    const int m0   = (wid & 1) * 32;
    const int n0   = (wid >> 1) * 32;
    const int arow = lane >> 2;
    const int acol = lane & 3;

    const float* xb = x + (size_t)b * Cin * HW;
    float acc[2][4][4];
#pragma unroll
    for (int ma = 0; ma < 2; ma++)
#pragma unroll
        for (int na = 0; na < 4; na++)
#pragma unroll
            for (int q = 0; q < 4; q++) acc[ma][na][q] = 0.f;

    // ---- prologue: stage chunk 0 into buffer 0 ----
    {
        const float4* wp = g_wP4;
#pragma unroll
        for (int j = 0; j < 5; j++)
            ((float4*)s_w)[tid + j * 256] = wp[tid + j * 256];
#pragma unroll
        for (int t = 0; t < 9; t++) {
            int T = wid * 9 + t;                 // 0..71
            int kkl = T >> 1, half = T & 1;
            int p = half * 32 + lane;
            int cc = kkl / 9, k = kkl - (kkl / 9) * 9;
            const float* xc = xb + cc * HW;
            int mi = p * 9 + k;
            float4 wv = s_mw[mi];
            int4  ov = s_mo[mi];
            float v = wv.x * __ldg(xc + ov.x) + wv.y * __ldg(xc + ov.y)
                    + wv.z * __ldg(xc + ov.z) + wv.w * __ldg(xc + ov.w);
            s_s[srow40(p, kpos(kkl))] = to_tf32(v);
        }
    }
    __syncthreads();

    for (int i = 0; i < NCH; i++) {
        const int cur = i & 1, nxt = cur ^ 1;
        const bool pf = (i + 1) < NCH;

        // ---- 1. prefetch chunk i+1 into registers ----
        float4 wreg[5];
        float g0[9], g1[9], g2[9], g3[9];
        if (pf) {
            const float4* wp = g_wP4 + (size_t)(i + 1) * (Cout * KP / 4);
#pragma unroll
            for (int j = 0; j < 5; j++) wreg[j] = __ldg(wp + tid + j * 256);
            const int c0n = (i + 1) * CH;
#pragma unroll
            for (int t = 0; t < 9; t++) {
                int T = wid * 9 + t;
                int kkl = T >> 1, half = T & 1;
                int p = half * 32 + lane;
                int cc = kkl / 9, k = kkl - (kkl / 9) * 9;
                const float* xc = xb + (c0n + cc) * HW;
                int4 ov = s_mo[p * 9 + k];
                g0[t] = __ldg(xc + ov.x);
                g1[t] = __ldg(xc + ov.y);
                g2[t] = __ldg(xc + ov.z);
                g3[t] = __ldg(xc + ov.w);
            }
        }

        // ---- 2. MMA on chunk i ----
        {
            const float* ss = s_s + cur * 2560;
            const float* sw = s_w + cur * 5120;
#pragma unroll
            for (int ks = 0; ks < 5; ks++) {
                const int ko = ks * 8 + 2 * acol;
                unsigned a[2][4];
#pragma unroll
                for (int ma = 0; ma < 2; ma++) {
                    const int row = m0 + ma * 16 + arow;
                    uint2 lo = *(const uint2*)(ss + srow40(row, ko));
                    uint2 hi = *(const uint2*)(ss + srow40(row + 8, ko));
                    a[ma][0] = lo.x; a[ma][1] = hi.x;
                    a[ma][2] = lo.y; a[ma][3] = hi.y;
                }
#pragma unroll
                for (int na = 0; na < 4; na++) {
                    uint2 bb = *(const uint2*)(sw + (n0 + na * 8 + arow) * KST + ko);
#pragma unroll
                    for (int ma = 0; ma < 2; ma++) {
                        asm volatile(
                            "mma.sync.aligned.m16n8k8.row.col.f32.tf32.tf32.f32 "
                            "{%0,%1,%2,%3}, {%4,%5,%6,%7}, {%8,%9}, {%0,%1,%2,%3};"
                            : "+f"(acc[ma][na][0]), "+f"(acc[ma][na][1]),
                              "+f"(acc[ma][na][2]), "+f"(acc[ma][na][3])
                            : "r"(a[ma][0]), "r"(a[ma][1]), "r"(a[ma][2]), "r"(a[ma][3]),
                              "r"(bb.x), "r"(bb.y));
                    }
                }
            }
        }

        // ---- 3. writeback chunk i+1 into buffer nxt ----
        if (pf) {
            float4* swn = (float4*)(s_w + nxt * 5120);
#pragma unroll
            for (int j = 0; j < 5; j++) swn[tid + j * 256] = wreg[j];
            float* ssn = s_s + nxt * 2560;
#pragma unroll
            for (int t = 0; t < 9; t++) {
                int T = wid * 9 + t;
                int kkl = T >> 1, half = T & 1;
                int p = half * 32 + lane;
                int cc = kkl / 9, k = kkl - (kkl / 9) * 9;
                float4 wv = s_mw[p * 9 + k];
                float v = wv.x * g0[t] + wv.y * g1[t] + wv.z * g2[t] + wv.w * g3[t];
                ssn[srow40(p, kpos(kkl))] = to_tf32(v);
            }
        }
        __syncthreads();
    }

    // ---- epilogue: fp32 bias add + stores ----
#pragma unroll
    for (int ma = 0; ma < 2; ma++) {
        int prow = hw0 + m0 + ma * 16 + arow;
#pragma unroll
        for (int na = 0; na < 4; na++) {
            int o = n0 + na * 8 + 2 * acol;
            float b0 = __ldg(bias + o);
            float b1 = __ldg(bias + o + 1);
            float* p0 = out + ((size_t)b * Cout + o) * HW + prow;
            float* p1 = p0 + HW;
            p0[0] = acc[ma][na][0] + b0;
            p1[0] = acc[ma][na][1] + b1;
            p0[8] = acc[ma][na][2] + b0;
            p1[8] = acc[ma][na][3] + b1;
        }
    }
}

// ---------------- launcher ----------------
extern "C" void kernel_launch(void* const* d_in, const int* in_sizes, int n_in,
                              void* d_out, int out_size) {
    const float* x        = (const float*)d_in[0];
    const float* offset_w = (const float*)d_in[1];
    const float* offset_b = (const float*)d_in[2];
    const float* mod_w    = (const float*)d_in[3];
    const float* mod_b    = (const float*)d_in[4];
    const float* w        = (const float*)d_in[5];
    const float* bias     = (const float*)d_in[6];
    float* out = (float*)d_out;

    const int SMEM = 9216 + 9216 + 20480 + 40960;   // 79872 B
    cudaFuncSetAttribute(main_kernel, cudaFuncAttributeMaxDynamicSharedMemorySize, SMEM);

    prep_weights_kernel<<<(NCH * Cout * KP + 255) / 256, 256>>>(w, offset_w, mod_w);
    offmask_kernel<<<NPIX / 64, 256>>>(x, offset_b, mod_b);
    main_kernel<<<NPIX / 64, 256, SMEM>>>(x, bias, out);
}